// round 2
// baseline (speedup 1.0000x reference)
#include <cuda_runtime.h>
#include <cstdint>

#define N_ATOMS 100000
#define N_EDGES 400000
#define N_MOLS  4096
#define ATOM_FDIM 133
#define BOND_FDIM 14
#define HIDDEN 300
#define N_LABELS 12
#define NPAD 320        // padded hidden width
#define KX 136          // padded atom feature dim
#define KE 16           // padded bond feature dim
#define KH 304          // padded hidden as K-dim

// ------------------------- scratch (static, no allocs) -------------------------
__device__ float g_xpad[(size_t)N_ATOMS * KX];
__device__ float g_eapad[(size_t)N_EDGES * KE];
__device__ float g_hv  [(size_t)N_ATOMS * NPAD];
__device__ float g_hv2 [(size_t)N_ATOMS * NPAD];
__device__ float g_P   [(size_t)N_ATOMS * NPAD];
__device__ float g_agg [(size_t)N_ATOMS * NPAD];
__device__ float g_E   [(size_t)N_EDGES * NPAD];
__device__ float g_mol [(size_t)N_MOLS * NPAD];
__device__ float g_ffn [(size_t)N_MOLS * NPAD];

__device__ float g_atomW[KX * NPAD];
__device__ float g_WiTop[KH * NPAD];
__device__ float g_WiBot[KE * NPAD];
__device__ float g_Wo   [2 * KH * NPAD];
__device__ float g_ffn1 [KH * NPAD];
__device__ float g_atomB[NPAD];
__device__ float g_WoB  [NPAD];
__device__ float g_ffn1B[NPAD];
__device__ float g_zeros[NPAD];   // stays zero

// ------------------------- helpers -------------------------
__device__ __forceinline__ unsigned long long pack2(float x) {
    unsigned long long r;
    asm("mov.b64 %0, {%1, %1};" : "=l"(r) : "f"(x));
    return r;
}

union U64F2 { unsigned long long u; float2 f; };

// ------------------------- repack: zero-padded copy -------------------------
__global__ void repack(float* __restrict__ dst, const float* __restrict__ src,
                       int dstR, int dstC, int srcR, int srcC, int srcRow0) {
    int idx = blockIdx.x * blockDim.x + threadIdx.x;
    if (idx >= dstR * dstC) return;
    int r = idx / dstC, c = idx - r * dstC;
    float v = 0.f;
    if (r < srcR && c < srcC) v = src[(size_t)(r + srcRow0) * srcC + c];
    dst[idx] = v;
}

__global__ void zerok(float4* __restrict__ p, int n4) {
    int i = blockIdx.x * blockDim.x + threadIdx.x;
    if (i < n4) p[i] = make_float4(0.f, 0.f, 0.f, 0.f);
}

// ------------------------- GEMM: C[M x 320] = relu?(A @ W + bias) -------------------------
// A is a virtual concat of A1 (K1 cols, stride lda1) and A2 (K2 cols, stride lda2).
// K1, K2 multiples of 8. W padded [K1+K2 x 320]. Uses packed fp32x2 FMA.
__global__ __launch_bounds__(256)
void gemm320(const float* __restrict__ A1, int lda1, int K1,
             const float* __restrict__ A2, int lda2, int K2,
             const float* __restrict__ W, const float* __restrict__ bias,
             float* __restrict__ C, int M, int doRelu) {
    __shared__ float As[8][64];
    __shared__ float Bs[8][NPAD];

    int tid = threadIdx.x;
    int tx = tid & 15;      // column group (handles cols tx*2 + j*32, j=0..9)
    int ty = tid >> 4;      // row group (4 rows each)
    int row0 = blockIdx.x * 64;

    unsigned long long acc[4][10];
    #pragma unroll
    for (int m = 0; m < 4; m++)
        #pragma unroll
        for (int j = 0; j < 10; j++) acc[m][j] = 0ULL;

    int Ktot = K1 + K2;
    int ar = tid >> 2;            // 0..63 : A-tile row
    int ak = (tid & 3) * 2;       // 0,2,4,6 : A-tile k pair

    for (int k0 = 0; k0 < Ktot; k0 += 8) {
        // --- load A tile (64 x 8) ---
        const float* Asrc; int lda; int kb;
        if (k0 < K1) { Asrc = A1; lda = lda1; kb = k0; }
        else         { Asrc = A2; lda = lda2; kb = k0 - K1; }
        float2 av = make_float2(0.f, 0.f);
        int grow = row0 + ar;
        if (grow < M) av = *(const float2*)(Asrc + (size_t)grow * lda + kb + ak);
        As[ak][ar] = av.x;
        As[ak + 1][ar] = av.y;
        // --- load B tile (8 x 320) ---
        const float2* Wsrc = (const float2*)(W + (size_t)k0 * NPAD);
        #pragma unroll
        for (int i = 0; i < 5; i++) {
            int idx = tid + i * 256;            // 0..1279 float2
            int bk = idx / 160;
            int bn = idx - bk * 160;
            float2 v = Wsrc[(size_t)bk * 160 + bn];
            *(float2*)&Bs[bk][bn * 2] = v;
        }
        __syncthreads();
        #pragma unroll
        for (int k = 0; k < 8; k++) {
            float4 a4 = *(const float4*)&As[k][ty * 4];
            unsigned long long b[10];
            #pragma unroll
            for (int j = 0; j < 10; j++)
                b[j] = *(const unsigned long long*)&Bs[k][(tx + j * 16) * 2];
            unsigned long long a2[4];
            a2[0] = pack2(a4.x); a2[1] = pack2(a4.y);
            a2[2] = pack2(a4.z); a2[3] = pack2(a4.w);
            #pragma unroll
            for (int m = 0; m < 4; m++)
                #pragma unroll
                for (int j = 0; j < 10; j++)
                    asm("fma.rn.f32x2 %0, %1, %2, %0;"
                        : "+l"(acc[m][j]) : "l"(a2[m]), "l"(b[j]));
        }
        __syncthreads();
    }

    #pragma unroll
    for (int m = 0; m < 4; m++) {
        int grow = row0 + ty * 4 + m;
        if (grow < M) {
            #pragma unroll
            for (int j = 0; j < 10; j++) {
                int col = (tx + j * 16) * 2;
                U64F2 u; u.u = acc[m][j];
                float2 v = u.f;
                float2 bv = *(const float2*)&bias[col];
                v.x += bv.x; v.y += bv.y;
                if (doRelu) { v.x = fmaxf(v.x, 0.f); v.y = fmaxf(v.y, 0.f); }
                *(float2*)(C + (size_t)grow * NPAD + col) = v;
            }
        }
    }
}

// ------------------------- edge scatter: agg[dst] += relu(P[src] + E[e]) -------------------------
__global__ void edge_scatter(const float* __restrict__ P, const float* __restrict__ E,
                             const int* __restrict__ src, const int* __restrict__ dst,
                             float* __restrict__ agg) {
    int w = (blockIdx.x * blockDim.x + threadIdx.x) >> 5;
    int lane = threadIdx.x & 31;
    if (w >= N_EDGES) return;
    int s = src[w], d = dst[w];
    const float4* Pr = (const float4*)(P + (size_t)s * NPAD);
    const float4* Er = (const float4*)(E + (size_t)w * NPAD);
    float* ag = agg + (size_t)d * NPAD;
    for (int c = lane; c < 75; c += 32) {      // 300 valid cols = 75 float4
        float4 p = Pr[c];
        float4 e = Er[c];
        float x0 = fmaxf(p.x + e.x, 0.f);
        float x1 = fmaxf(p.y + e.y, 0.f);
        float x2 = fmaxf(p.z + e.z, 0.f);
        float x3 = fmaxf(p.w + e.w, 0.f);
        atomicAdd(ag + 4 * c + 0, x0);
        atomicAdd(ag + 4 * c + 1, x1);
        atomicAdd(ag + 4 * c + 2, x2);
        atomicAdd(ag + 4 * c + 3, x3);
    }
}

// ------------------------- mol scatter: mol[batch[a]] += h_v[a] -------------------------
__global__ void mol_scatter(const float* __restrict__ hv, const int* __restrict__ batch,
                            float* __restrict__ mol) {
    int w = (blockIdx.x * blockDim.x + threadIdx.x) >> 5;
    int lane = threadIdx.x & 31;
    if (w >= N_ATOMS) return;
    int b = batch[w];
    const float4* hr = (const float4*)(hv + (size_t)w * NPAD);
    float* mr = mol + (size_t)b * NPAD;
    for (int c = lane; c < 75; c += 32) {
        float4 v = hr[c];
        atomicAdd(mr + 4 * c + 0, v.x);
        atomicAdd(mr + 4 * c + 1, v.y);
        atomicAdd(mr + 4 * c + 2, v.z);
        atomicAdd(mr + 4 * c + 3, v.w);
    }
}

// ------------------------- final: out = relu'd_ffn @ ffn2 + b2 -------------------------
__global__ void finalk(const float* __restrict__ F, const float* __restrict__ W2,
                       const float* __restrict__ b2, float* __restrict__ out) {
    int w = (blockIdx.x * blockDim.x + threadIdx.x) >> 5;
    int lane = threadIdx.x & 31;
    if (w >= N_MOLS) return;
    float acc = (lane < 12) ? b2[lane] : 0.f;
    const float* f = F + (size_t)w * NPAD;
    for (int j = 0; j < HIDDEN; j++) {
        float fv = __ldg(f + j);
        if (lane < 12) acc = fmaf(fv, W2[j * 12 + lane], acc);
    }
    if (lane < 12) out[w * 12 + lane] = acc;
}

// ------------------------- host launch -------------------------
static inline dim3 rep_grid(int n) { return dim3((n + 255) / 256); }

extern "C" void kernel_launch(void* const* d_in, const int* in_sizes, int n_in,
                              void* d_out, int out_size) {
    const float* x      = (const float*)d_in[0];
    const int*   ei     = (const int*)  d_in[1];   // [2, N_EDGES]
    const float* ea     = (const float*)d_in[2];
    const int*   batch  = (const int*)  d_in[3];
    const float* atom_W = (const float*)d_in[4];
    const float* atom_b = (const float*)d_in[5];
    // d_in[6], d_in[7]: bond_W / bond_b  -> dead code
    const float* Wi     = (const float*)d_in[8];
    // d_in[9]: Wh -> dead code
    const float* Wo     = (const float*)d_in[10];
    const float* Wo_b   = (const float*)d_in[11];
    const float* ffn1_W = (const float*)d_in[12];
    const float* ffn1_b = (const float*)d_in[13];
    const float* ffn2_W = (const float*)d_in[14];
    const float* ffn2_b = (const float*)d_in[15];
    float* out = (float*)d_out;

    float *p_xpad, *p_eapad, *p_hv, *p_hv2, *p_P, *p_agg, *p_E, *p_mol, *p_ffn;
    float *p_atomW, *p_WiTop, *p_WiBot, *p_Wo, *p_ffn1;
    float *p_atomB, *p_WoB, *p_ffn1B, *p_zeros;
    cudaGetSymbolAddress((void**)&p_xpad,  g_xpad);
    cudaGetSymbolAddress((void**)&p_eapad, g_eapad);
    cudaGetSymbolAddress((void**)&p_hv,    g_hv);
    cudaGetSymbolAddress((void**)&p_hv2,   g_hv2);
    cudaGetSymbolAddress((void**)&p_P,     g_P);
    cudaGetSymbolAddress((void**)&p_agg,   g_agg);
    cudaGetSymbolAddress((void**)&p_E,     g_E);
    cudaGetSymbolAddress((void**)&p_mol,   g_mol);
    cudaGetSymbolAddress((void**)&p_ffn,   g_ffn);
    cudaGetSymbolAddress((void**)&p_atomW, g_atomW);
    cudaGetSymbolAddress((void**)&p_WiTop, g_WiTop);
    cudaGetSymbolAddress((void**)&p_WiBot, g_WiBot);
    cudaGetSymbolAddress((void**)&p_Wo,    g_Wo);
    cudaGetSymbolAddress((void**)&p_ffn1,  g_ffn1);
    cudaGetSymbolAddress((void**)&p_atomB, g_atomB);
    cudaGetSymbolAddress((void**)&p_WoB,   g_WoB);
    cudaGetSymbolAddress((void**)&p_ffn1B, g_ffn1B);
    cudaGetSymbolAddress((void**)&p_zeros, g_zeros);

    // ---- repack inputs / weights into padded layouts ----
    repack<<<rep_grid(N_ATOMS * KX), 256>>>(p_xpad, x, N_ATOMS, KX, N_ATOMS, ATOM_FDIM, 0);
    repack<<<rep_grid(N_EDGES * KE), 256>>>(p_eapad, ea, N_EDGES, KE, N_EDGES, BOND_FDIM, 0);
    repack<<<rep_grid(KX * NPAD), 256>>>(p_atomW, atom_W, KX, NPAD, ATOM_FDIM, HIDDEN, 0);
    repack<<<rep_grid(KH * NPAD), 256>>>(p_WiTop, Wi, KH, NPAD, HIDDEN, HIDDEN, 0);
    repack<<<rep_grid(KE * NPAD), 256>>>(p_WiBot, Wi, KE, NPAD, BOND_FDIM, HIDDEN, HIDDEN);
    repack<<<rep_grid(KH * NPAD), 256>>>(p_Wo, Wo, KH, NPAD, HIDDEN, HIDDEN, 0);
    repack<<<rep_grid(KH * NPAD), 256>>>(p_Wo + KH * NPAD, Wo, KH, NPAD, HIDDEN, HIDDEN, HIDDEN);
    repack<<<rep_grid(KH * NPAD), 256>>>(p_ffn1, ffn1_W, KH, NPAD, HIDDEN, HIDDEN, 0);
    repack<<<rep_grid(NPAD), 256>>>(p_atomB, atom_b, 1, NPAD, 1, HIDDEN, 0);
    repack<<<rep_grid(NPAD), 256>>>(p_WoB, Wo_b, 1, NPAD, 1, HIDDEN, 0);
    repack<<<rep_grid(NPAD), 256>>>(p_ffn1B, ffn1_b, 1, NPAD, 1, HIDDEN, 0);

    dim3 gAtom((N_ATOMS + 63) / 64), gEdge((N_EDGES + 63) / 64), gMol((N_MOLS + 63) / 64);

    // h_v = relu(x @ atom_W + atom_b)
    gemm320<<<gAtom, 256>>>(p_xpad, KX, KX, nullptr, 0, 0, p_atomW, p_atomB, p_hv, N_ATOMS, 1);
    // E = edge_attr @ Wi_bot   (loop-invariant)
    gemm320<<<gEdge, 256>>>(p_eapad, KE, KE, nullptr, 0, 0, p_WiBot, p_zeros, p_E, N_EDGES, 0);

    int edge_blocks = (N_EDGES * 32 + 255) / 256;
    int atom_warp_blocks = (N_ATOMS * 32 + 255) / 256;

    float* cur = p_hv;
    float* nxt = p_hv2;
    for (int d = 0; d < 3; d++) {
        // P = h_v @ Wi_top
        gemm320<<<gAtom, 256>>>(cur, NPAD, KH, nullptr, 0, 0, p_WiTop, p_zeros, p_P, N_ATOMS, 0);
        // agg = 0; agg[dst] += relu(P[src] + E)
        zerok<<<(N_ATOMS * NPAD / 4 + 255) / 256, 256>>>((float4*)p_agg, N_ATOMS * NPAD / 4);
        edge_scatter<<<edge_blocks, 256>>>(p_P, p_E, ei, ei + N_EDGES, p_agg);
        // h_v = relu([h_v, agg] @ Wo + Wo_b)
        gemm320<<<gAtom, 256>>>(cur, NPAD, KH, p_agg, NPAD, KH, p_Wo, p_WoB, nxt, N_ATOMS, 1);
        float* t = cur; cur = nxt; nxt = t;
    }

    // mol_repr = segment_sum(h_v, batch)
    zerok<<<(N_MOLS * NPAD / 4 + 255) / 256, 256>>>((float4*)p_mol, N_MOLS * NPAD / 4);
    mol_scatter<<<atom_warp_blocks, 256>>>(cur, batch, p_mol);
    // ffn = relu(mol @ ffn1 + b1)
    gemm320<<<gMol, 256>>>(p_mol, NPAD, KH, nullptr, 0, 0, p_ffn1, p_ffn1B, p_ffn, N_MOLS, 1);
    // out = ffn @ ffn2 + b2
    finalk<<<(N_MOLS * 32 + 255) / 256, 256>>>(p_ffn, ffn2_W, ffn2_b, out);
}

// round 3
// speedup vs baseline: 1.0006x; 1.0006x over previous
#include <cuda_runtime.h>
#include <cstdint>

#define N_ATOMS 100000
#define N_EDGES 400000
#define N_MOLS  4096
#define ATOM_FDIM 133
#define BOND_FDIM 14
#define HIDDEN 300
#define N_LABELS 12
#define NPAD 320        // padded hidden width
#define KX 136          // padded atom feature dim
#define KE 16           // padded bond feature dim
#define KH 304          // padded hidden as K-dim

// ------------------------- scratch (static, no allocs) -------------------------
__device__ float g_xpad[(size_t)N_ATOMS * KX];
__device__ float g_eapad[(size_t)N_EDGES * KE];
__device__ float g_hv  [(size_t)N_ATOMS * NPAD];
__device__ float g_hv2 [(size_t)N_ATOMS * NPAD];
__device__ float g_P   [(size_t)N_ATOMS * NPAD];
__device__ float g_agg [(size_t)N_ATOMS * NPAD];
__device__ float g_E   [(size_t)N_EDGES * NPAD];
__device__ float g_mol [(size_t)N_MOLS * NPAD];
__device__ float g_ffn [(size_t)N_MOLS * NPAD];

__device__ float g_atomW[KX * NPAD];
__device__ float g_WiTop[KH * NPAD];
__device__ float g_WiBot[KE * NPAD];
__device__ float g_Wo   [2 * KH * NPAD];
__device__ float g_ffn1 [KH * NPAD];
__device__ float g_atomB[NPAD];
__device__ float g_WoB  [NPAD];
__device__ float g_ffn1B[NPAD];
__device__ float g_zeros[NPAD];   // stays zero

// ------------------------- helpers -------------------------
__device__ __forceinline__ unsigned long long pack2(float x) {
    unsigned long long r;
    asm("mov.b64 %0, {%1, %1};" : "=l"(r) : "f"(x));
    return r;
}

union U64F2 { unsigned long long u; float2 f; };

// ------------------------- repack: zero-padded copy -------------------------
__global__ void repack(float* __restrict__ dst, const float* __restrict__ src,
                       int dstR, int dstC, int srcR, int srcC, int srcRow0) {
    int idx = blockIdx.x * blockDim.x + threadIdx.x;
    if (idx >= dstR * dstC) return;
    int r = idx / dstC, c = idx - r * dstC;
    float v = 0.f;
    if (r < srcR && c < srcC) v = src[(size_t)(r + srcRow0) * srcC + c];
    dst[idx] = v;
}

__global__ void zerok(float4* __restrict__ p, int n4) {
    int i = blockIdx.x * blockDim.x + threadIdx.x;
    if (i < n4) p[i] = make_float4(0.f, 0.f, 0.f, 0.f);
}

// ------------------------- GEMM: C[M x 320] = relu?(A @ W + bias) -------------------------
// A is a virtual concat of A1 (K1 cols, stride lda1) and A2 (K2 cols, stride lda2).
// K1, K2 multiples of 8. W padded [K1+K2 x 320]. Uses packed fp32x2 FMA.
__global__ __launch_bounds__(256)
void gemm320(const float* __restrict__ A1, int lda1, int K1,
             const float* __restrict__ A2, int lda2, int K2,
             const float* __restrict__ W, const float* __restrict__ bias,
             float* __restrict__ C, int M, int doRelu) {
    __shared__ float As[8][64];
    __shared__ float Bs[8][NPAD];

    int tid = threadIdx.x;
    int tx = tid & 15;      // column group (handles cols tx*2 + j*32, j=0..9)
    int ty = tid >> 4;      // row group (4 rows each)
    int row0 = blockIdx.x * 64;

    unsigned long long acc[4][10];
    #pragma unroll
    for (int m = 0; m < 4; m++)
        #pragma unroll
        for (int j = 0; j < 10; j++) acc[m][j] = 0ULL;

    int Ktot = K1 + K2;
    int ar = tid >> 2;            // 0..63 : A-tile row
    int ak = (tid & 3) * 2;       // 0,2,4,6 : A-tile k pair

    for (int k0 = 0; k0 < Ktot; k0 += 8) {
        // --- load A tile (64 x 8) ---
        const float* Asrc; int lda; int kb;
        if (k0 < K1) { Asrc = A1; lda = lda1; kb = k0; }
        else         { Asrc = A2; lda = lda2; kb = k0 - K1; }
        float2 av = make_float2(0.f, 0.f);
        int grow = row0 + ar;
        if (grow < M) av = *(const float2*)(Asrc + (size_t)grow * lda + kb + ak);
        As[ak][ar] = av.x;
        As[ak + 1][ar] = av.y;
        // --- load B tile (8 x 320) ---
        const float2* Wsrc = (const float2*)(W + (size_t)k0 * NPAD);
        #pragma unroll
        for (int i = 0; i < 5; i++) {
            int idx = tid + i * 256;            // 0..1279 float2
            int bk = idx / 160;
            int bn = idx - bk * 160;
            float2 v = Wsrc[(size_t)bk * 160 + bn];
            *(float2*)&Bs[bk][bn * 2] = v;
        }
        __syncthreads();
        #pragma unroll
        for (int k = 0; k < 8; k++) {
            float4 a4 = *(const float4*)&As[k][ty * 4];
            unsigned long long b[10];
            #pragma unroll
            for (int j = 0; j < 10; j++)
                b[j] = *(const unsigned long long*)&Bs[k][(tx + j * 16) * 2];
            unsigned long long a2[4];
            a2[0] = pack2(a4.x); a2[1] = pack2(a4.y);
            a2[2] = pack2(a4.z); a2[3] = pack2(a4.w);
            #pragma unroll
            for (int m = 0; m < 4; m++)
                #pragma unroll
                for (int j = 0; j < 10; j++)
                    asm("fma.rn.f32x2 %0, %1, %2, %0;"
                        : "+l"(acc[m][j]) : "l"(a2[m]), "l"(b[j]));
        }
        __syncthreads();
    }

    #pragma unroll
    for (int m = 0; m < 4; m++) {
        int grow = row0 + ty * 4 + m;
        if (grow < M) {
            #pragma unroll
            for (int j = 0; j < 10; j++) {
                int col = (tx + j * 16) * 2;
                U64F2 u; u.u = acc[m][j];
                float2 v = u.f;
                float2 bv = *(const float2*)&bias[col];
                v.x += bv.x; v.y += bv.y;
                if (doRelu) { v.x = fmaxf(v.x, 0.f); v.y = fmaxf(v.y, 0.f); }
                *(float2*)(C + (size_t)grow * NPAD + col) = v;
            }
        }
    }
}

// ------------------------- edge scatter: agg[dst] += relu(P[src] + E[e]) -------------------------
__global__ void edge_scatter(const float* __restrict__ P, const float* __restrict__ E,
                             const int* __restrict__ src, const int* __restrict__ dst,
                             float* __restrict__ agg) {
    int w = (blockIdx.x * blockDim.x + threadIdx.x) >> 5;
    int lane = threadIdx.x & 31;
    if (w >= N_EDGES) return;
    int s = src[w], d = dst[w];
    const float4* Pr = (const float4*)(P + (size_t)s * NPAD);
    const float4* Er = (const float4*)(E + (size_t)w * NPAD);
    float* ag = agg + (size_t)d * NPAD;
    for (int c = lane; c < 75; c += 32) {      // 300 valid cols = 75 float4
        float4 p = Pr[c];
        float4 e = Er[c];
        float x0 = fmaxf(p.x + e.x, 0.f);
        float x1 = fmaxf(p.y + e.y, 0.f);
        float x2 = fmaxf(p.z + e.z, 0.f);
        float x3 = fmaxf(p.w + e.w, 0.f);
        atomicAdd(ag + 4 * c + 0, x0);
        atomicAdd(ag + 4 * c + 1, x1);
        atomicAdd(ag + 4 * c + 2, x2);
        atomicAdd(ag + 4 * c + 3, x3);
    }
}

// ------------------------- mol scatter: mol[batch[a]] += h_v[a] -------------------------
__global__ void mol_scatter(const float* __restrict__ hv, const int* __restrict__ batch,
                            float* __restrict__ mol) {
    int w = (blockIdx.x * blockDim.x + threadIdx.x) >> 5;
    int lane = threadIdx.x & 31;
    if (w >= N_ATOMS) return;
    int b = batch[w];
    const float4* hr = (const float4*)(hv + (size_t)w * NPAD);
    float* mr = mol + (size_t)b * NPAD;
    for (int c = lane; c < 75; c += 32) {
        float4 v = hr[c];
        atomicAdd(mr + 4 * c + 0, v.x);
        atomicAdd(mr + 4 * c + 1, v.y);
        atomicAdd(mr + 4 * c + 2, v.z);
        atomicAdd(mr + 4 * c + 3, v.w);
    }
}

// ------------------------- final: out = relu'd_ffn @ ffn2 + b2 -------------------------
__global__ void finalk(const float* __restrict__ F, const float* __restrict__ W2,
                       const float* __restrict__ b2, float* __restrict__ out) {
    int w = (blockIdx.x * blockDim.x + threadIdx.x) >> 5;
    int lane = threadIdx.x & 31;
    if (w >= N_MOLS) return;
    float acc = (lane < 12) ? b2[lane] : 0.f;
    const float* f = F + (size_t)w * NPAD;
    for (int j = 0; j < HIDDEN; j++) {
        float fv = __ldg(f + j);
        if (lane < 12) acc = fmaf(fv, W2[j * 12 + lane], acc);
    }
    if (lane < 12) out[w * 12 + lane] = acc;
}

// ------------------------- host launch -------------------------
static inline dim3 rep_grid(int n) { return dim3((n + 255) / 256); }

extern "C" void kernel_launch(void* const* d_in, const int* in_sizes, int n_in,
                              void* d_out, int out_size) {
    const float* x      = (const float*)d_in[0];
    const int*   ei     = (const int*)  d_in[1];   // [2, N_EDGES]
    const float* ea     = (const float*)d_in[2];
    const int*   batch  = (const int*)  d_in[3];
    const float* atom_W = (const float*)d_in[4];
    const float* atom_b = (const float*)d_in[5];
    // d_in[6], d_in[7]: bond_W / bond_b  -> dead code
    const float* Wi     = (const float*)d_in[8];
    // d_in[9]: Wh -> dead code
    const float* Wo     = (const float*)d_in[10];
    const float* Wo_b   = (const float*)d_in[11];
    const float* ffn1_W = (const float*)d_in[12];
    const float* ffn1_b = (const float*)d_in[13];
    const float* ffn2_W = (const float*)d_in[14];
    const float* ffn2_b = (const float*)d_in[15];
    float* out = (float*)d_out;

    float *p_xpad, *p_eapad, *p_hv, *p_hv2, *p_P, *p_agg, *p_E, *p_mol, *p_ffn;
    float *p_atomW, *p_WiTop, *p_WiBot, *p_Wo, *p_ffn1;
    float *p_atomB, *p_WoB, *p_ffn1B, *p_zeros;
    cudaGetSymbolAddress((void**)&p_xpad,  g_xpad);
    cudaGetSymbolAddress((void**)&p_eapad, g_eapad);
    cudaGetSymbolAddress((void**)&p_hv,    g_hv);
    cudaGetSymbolAddress((void**)&p_hv2,   g_hv2);
    cudaGetSymbolAddress((void**)&p_P,     g_P);
    cudaGetSymbolAddress((void**)&p_agg,   g_agg);
    cudaGetSymbolAddress((void**)&p_E,     g_E);
    cudaGetSymbolAddress((void**)&p_mol,   g_mol);
    cudaGetSymbolAddress((void**)&p_ffn,   g_ffn);
    cudaGetSymbolAddress((void**)&p_atomW, g_atomW);
    cudaGetSymbolAddress((void**)&p_WiTop, g_WiTop);
    cudaGetSymbolAddress((void**)&p_WiBot, g_WiBot);
    cudaGetSymbolAddress((void**)&p_Wo,    g_Wo);
    cudaGetSymbolAddress((void**)&p_ffn1,  g_ffn1);
    cudaGetSymbolAddress((void**)&p_atomB, g_atomB);
    cudaGetSymbolAddress((void**)&p_WoB,   g_WoB);
    cudaGetSymbolAddress((void**)&p_ffn1B, g_ffn1B);
    cudaGetSymbolAddress((void**)&p_zeros, g_zeros);

    // ---- repack inputs / weights into padded layouts ----
    repack<<<rep_grid(N_ATOMS * KX), 256>>>(p_xpad, x, N_ATOMS, KX, N_ATOMS, ATOM_FDIM, 0);
    repack<<<rep_grid(N_EDGES * KE), 256>>>(p_eapad, ea, N_EDGES, KE, N_EDGES, BOND_FDIM, 0);
    repack<<<rep_grid(KX * NPAD), 256>>>(p_atomW, atom_W, KX, NPAD, ATOM_FDIM, HIDDEN, 0);
    repack<<<rep_grid(KH * NPAD), 256>>>(p_WiTop, Wi, KH, NPAD, HIDDEN, HIDDEN, 0);
    repack<<<rep_grid(KE * NPAD), 256>>>(p_WiBot, Wi, KE, NPAD, BOND_FDIM, HIDDEN, HIDDEN);
    repack<<<rep_grid(KH * NPAD), 256>>>(p_Wo, Wo, KH, NPAD, HIDDEN, HIDDEN, 0);
    repack<<<rep_grid(KH * NPAD), 256>>>(p_Wo + KH * NPAD, Wo, KH, NPAD, HIDDEN, HIDDEN, HIDDEN);
    repack<<<rep_grid(KH * NPAD), 256>>>(p_ffn1, ffn1_W, KH, NPAD, HIDDEN, HIDDEN, 0);
    repack<<<rep_grid(NPAD), 256>>>(p_atomB, atom_b, 1, NPAD, 1, HIDDEN, 0);
    repack<<<rep_grid(NPAD), 256>>>(p_WoB, Wo_b, 1, NPAD, 1, HIDDEN, 0);
    repack<<<rep_grid(NPAD), 256>>>(p_ffn1B, ffn1_b, 1, NPAD, 1, HIDDEN, 0);

    dim3 gAtom((N_ATOMS + 63) / 64), gEdge((N_EDGES + 63) / 64), gMol((N_MOLS + 63) / 64);

    // h_v = relu(x @ atom_W + atom_b)
    gemm320<<<gAtom, 256>>>(p_xpad, KX, KX, nullptr, 0, 0, p_atomW, p_atomB, p_hv, N_ATOMS, 1);
    // E = edge_attr @ Wi_bot   (loop-invariant)
    gemm320<<<gEdge, 256>>>(p_eapad, KE, KE, nullptr, 0, 0, p_WiBot, p_zeros, p_E, N_EDGES, 0);

    int edge_blocks = (N_EDGES * 32 + 255) / 256;
    int atom_warp_blocks = (N_ATOMS * 32 + 255) / 256;

    float* cur = p_hv;
    float* nxt = p_hv2;
    for (int d = 0; d < 3; d++) {
        // P = h_v @ Wi_top
        gemm320<<<gAtom, 256>>>(cur, NPAD, KH, nullptr, 0, 0, p_WiTop, p_zeros, p_P, N_ATOMS, 0);
        // agg = 0; agg[dst] += relu(P[src] + E)
        zerok<<<(N_ATOMS * NPAD / 4 + 255) / 256, 256>>>((float4*)p_agg, N_ATOMS * NPAD / 4);
        edge_scatter<<<edge_blocks, 256>>>(p_P, p_E, ei, ei + N_EDGES, p_agg);
        // h_v = relu([h_v, agg] @ Wo + Wo_b)
        gemm320<<<gAtom, 256>>>(cur, NPAD, KH, p_agg, NPAD, KH, p_Wo, p_WoB, nxt, N_ATOMS, 1);
        float* t = cur; cur = nxt; nxt = t;
    }

    // mol_repr = segment_sum(h_v, batch)
    zerok<<<(N_MOLS * NPAD / 4 + 255) / 256, 256>>>((float4*)p_mol, N_MOLS * NPAD / 4);
    mol_scatter<<<atom_warp_blocks, 256>>>(cur, batch, p_mol);
    // ffn = relu(mol @ ffn1 + b1)
    gemm320<<<gMol, 256>>>(p_mol, NPAD, KH, nullptr, 0, 0, p_ffn1, p_ffn1B, p_ffn, N_MOLS, 1);
    // out = ffn @ ffn2 + b2
    finalk<<<(N_MOLS * 32 + 255) / 256, 256>>>(p_ffn, ffn2_W, ffn2_b, out);
}

// round 4
// speedup vs baseline: 1.5010x; 1.5001x over previous
#include <cuda_runtime.h>
#include <cstdint>

#define N_ATOMS 100000
#define N_EDGES 400000
#define N_MOLS  4096
#define ATOM_FDIM 133
#define BOND_FDIM 14
#define HIDDEN 300
#define N_LABELS 12
#define NPAD 320        // padded hidden width
#define KX 144          // padded atom feature dim (multiple of 16)
#define KE 16           // padded bond feature dim
#define KH 304          // padded hidden as K-dim (multiple of 16)

#define BM 128
#define BN 64
#define BK 16

// ------------------------- scratch (static, no allocs) -------------------------
__device__ float g_xpad[(size_t)N_ATOMS * KX];
__device__ float g_eapad[(size_t)N_EDGES * KE];
__device__ float g_hv  [(size_t)N_ATOMS * NPAD];
__device__ float g_hv2 [(size_t)N_ATOMS * NPAD];
__device__ float g_P   [(size_t)N_ATOMS * NPAD];
__device__ float g_agg [(size_t)N_ATOMS * NPAD];
__device__ float g_E   [(size_t)N_EDGES * NPAD];
__device__ float g_mol [(size_t)N_MOLS * NPAD];
__device__ float g_ffn [(size_t)N_MOLS * NPAD];

__device__ float g_atomW[KX * NPAD];
__device__ float g_WiTop[KH * NPAD];
__device__ float g_WiBot[KE * NPAD];
__device__ float g_Wo   [2 * KH * NPAD];
__device__ float g_ffn1 [KH * NPAD];
__device__ float g_atomB[NPAD];
__device__ float g_WoB  [NPAD];
__device__ float g_ffn1B[NPAD];
__device__ float g_zeros[NPAD];   // stays zero

// ------------------------- helpers -------------------------
__device__ __forceinline__ float tf32r(float x) {
    asm("cvt.rna.tf32.f32 %0, %0;" : "+f"(x));
    return x;
}

// ------------------------- repack: zero-padded copy -------------------------
__global__ void repack(float* __restrict__ dst, const float* __restrict__ src,
                       int dstR, int dstC, int srcR, int srcC, int srcRow0) {
    int idx = blockIdx.x * blockDim.x + threadIdx.x;
    if (idx >= dstR * dstC) return;
    int r = idx / dstC, c = idx - r * dstC;
    float v = 0.f;
    if (r < srcR && c < srcC) v = src[(size_t)(r + srcRow0) * srcC + c];
    dst[idx] = v;
}

__global__ void zerok(float4* __restrict__ p, int n4) {
    int i = blockIdx.x * blockDim.x + threadIdx.x;
    if (i < n4) p[i] = make_float4(0.f, 0.f, 0.f, 0.f);
}

// ------------------------- tf32 tensor-core GEMM -------------------------
// C[M x 320] = relu?(A @ W + bias), A = virtual concat of A1 (K1 cols) and A2 (K2 cols).
// K1, K2 multiples of 16. W padded [K1+K2 x 320].
// Block tile 128x64, BK=16. 8 warps in 4(m) x 2(n); warp tile 32x32 via
// mma.sync.m16n8k8 tf32 (2 m-tiles x 4 n-tiles, 4 accs each).
__global__ __launch_bounds__(256)
void gemm_tf32(const float* __restrict__ A1, int lda1, int K1,
               const float* __restrict__ A2, int lda2, int K2,
               const float* __restrict__ W, const float* __restrict__ bias,
               float* __restrict__ C, int M, int doRelu) {
    __shared__ float As[BK][132];   // k-major, pad 132 -> conflict-free frag loads
    __shared__ float Bs[BK][68];    // k-major, pad 68

    const int tid  = threadIdx.x;
    const int lane = tid & 31;
    const int wid  = tid >> 5;
    const int warpM0 = (wid >> 1) << 5;   // 0,32,64,96
    const int warpN0 = (wid & 1) << 5;    // 0,32
    const int row0 = blockIdx.x * BM;
    const int n0   = blockIdx.y * BN;

    float acc[2][4][4];
    #pragma unroll
    for (int mt = 0; mt < 2; mt++)
        #pragma unroll
        for (int nt = 0; nt < 4; nt++)
            #pragma unroll
            for (int i = 0; i < 4; i++) acc[mt][nt][i] = 0.f;

    const int am  = tid >> 2;          // 0..63 (tile row, +64 for second half)
    const int akq = (tid & 3) << 2;    // k base 0,4,8,12
    const int bkr = tid >> 4;          // 0..15 (B tile k row)
    const int bnc = (tid & 15) << 2;   // B tile col base

    const int Ktot = K1 + K2;
    const int fr = lane >> 2;
    const int fc = lane & 3;

    float4 ar0, ar1, br;

    // prefetch tile k0 = 0
    {
        const float* Asrc = (0 < K1) ? A1 : A2;
        int lda = (0 < K1) ? lda1 : lda2;
        int kb  = (0 < K1) ? 0 : -K1;
        int g0 = row0 + am;
        ar0 = make_float4(0.f, 0.f, 0.f, 0.f);
        ar1 = ar0;
        if (g0 < M)      ar0 = *(const float4*)(Asrc + (size_t)g0 * lda + kb + akq);
        if (g0 + 64 < M) ar1 = *(const float4*)(Asrc + (size_t)(g0 + 64) * lda + kb + akq);
        br = *(const float4*)(W + (size_t)bkr * NPAD + n0 + bnc);
    }

    for (int k0 = 0; k0 < Ktot; k0 += BK) {
        // store staged tile to SMEM (with tf32 round-to-nearest)
        As[akq + 0][am] = tf32r(ar0.x);
        As[akq + 1][am] = tf32r(ar0.y);
        As[akq + 2][am] = tf32r(ar0.z);
        As[akq + 3][am] = tf32r(ar0.w);
        As[akq + 0][am + 64] = tf32r(ar1.x);
        As[akq + 1][am + 64] = tf32r(ar1.y);
        As[akq + 2][am + 64] = tf32r(ar1.z);
        As[akq + 3][am + 64] = tf32r(ar1.w);
        Bs[bkr][bnc + 0] = tf32r(br.x);
        Bs[bkr][bnc + 1] = tf32r(br.y);
        Bs[bkr][bnc + 2] = tf32r(br.z);
        Bs[bkr][bnc + 3] = tf32r(br.w);
        __syncthreads();

        // prefetch next tile (overlaps with MMA below)
        int kn = k0 + BK;
        if (kn < Ktot) {
            const float* Asrc = (kn < K1) ? A1 : A2;
            int lda = (kn < K1) ? lda1 : lda2;
            int kb  = (kn < K1) ? kn : kn - K1;
            int g0 = row0 + am;
            ar0 = make_float4(0.f, 0.f, 0.f, 0.f);
            ar1 = ar0;
            if (g0 < M)      ar0 = *(const float4*)(Asrc + (size_t)g0 * lda + kb + akq);
            if (g0 + 64 < M) ar1 = *(const float4*)(Asrc + (size_t)(g0 + 64) * lda + kb + akq);
            br = *(const float4*)(W + (size_t)(kn + bkr) * NPAD + n0 + bnc);
        }

        // compute: 2 k8 steps
        #pragma unroll
        for (int ks = 0; ks < 2; ks++) {
            const int kk = ks * 8;
            uint32_t a[2][4], b[4][2];
            #pragma unroll
            for (int mt = 0; mt < 2; mt++) {
                int mr = warpM0 + mt * 16 + fr;
                a[mt][0] = __float_as_uint(As[kk + fc][mr]);
                a[mt][1] = __float_as_uint(As[kk + fc][mr + 8]);
                a[mt][2] = __float_as_uint(As[kk + fc + 4][mr]);
                a[mt][3] = __float_as_uint(As[kk + fc + 4][mr + 8]);
            }
            #pragma unroll
            for (int nt = 0; nt < 4; nt++) {
                int nc = warpN0 + nt * 8 + fr;
                b[nt][0] = __float_as_uint(Bs[kk + fc][nc]);
                b[nt][1] = __float_as_uint(Bs[kk + fc + 4][nc]);
            }
            #pragma unroll
            for (int mt = 0; mt < 2; mt++)
                #pragma unroll
                for (int nt = 0; nt < 4; nt++)
                    asm volatile(
                        "mma.sync.aligned.m16n8k8.row.col.f32.tf32.tf32.f32 "
                        "{%0,%1,%2,%3}, {%4,%5,%6,%7}, {%8,%9}, {%0,%1,%2,%3};"
                        : "+f"(acc[mt][nt][0]), "+f"(acc[mt][nt][1]),
                          "+f"(acc[mt][nt][2]), "+f"(acc[mt][nt][3])
                        : "r"(a[mt][0]), "r"(a[mt][1]), "r"(a[mt][2]), "r"(a[mt][3]),
                          "r"(b[nt][0]), "r"(b[nt][1]));
        }
        __syncthreads();
    }

    // epilogue
    #pragma unroll
    for (int mt = 0; mt < 2; mt++) {
        int r = row0 + warpM0 + mt * 16 + fr;
        #pragma unroll
        for (int nt = 0; nt < 4; nt++) {
            int cbase = n0 + warpN0 + nt * 8 + (fc << 1);
            float2 bv = *(const float2*)&bias[cbase];
            if (r < M) {
                float2 v = make_float2(acc[mt][nt][0] + bv.x, acc[mt][nt][1] + bv.y);
                if (doRelu) { v.x = fmaxf(v.x, 0.f); v.y = fmaxf(v.y, 0.f); }
                *(float2*)(C + (size_t)r * NPAD + cbase) = v;
            }
            if (r + 8 < M) {
                float2 v = make_float2(acc[mt][nt][2] + bv.x, acc[mt][nt][3] + bv.y);
                if (doRelu) { v.x = fmaxf(v.x, 0.f); v.y = fmaxf(v.y, 0.f); }
                *(float2*)(C + (size_t)(r + 8) * NPAD + cbase) = v;
            }
        }
    }
}

// ------------------------- edge scatter: agg[dst] += relu(P[src] + E[e]) -------------------------
__global__ void edge_scatter(const float* __restrict__ P, const float* __restrict__ E,
                             const int* __restrict__ src, const int* __restrict__ dst,
                             float* __restrict__ agg) {
    int w = (blockIdx.x * blockDim.x + threadIdx.x) >> 5;
    int lane = threadIdx.x & 31;
    if (w >= N_EDGES) return;
    int s = src[w], d = dst[w];
    const float4* Pr = (const float4*)(P + (size_t)s * NPAD);
    const float4* Er = (const float4*)(E + (size_t)w * NPAD);
    float* ag = agg + (size_t)d * NPAD;
    for (int c = lane; c < 75; c += 32) {      // 300 valid cols = 75 float4
        float4 p = Pr[c];
        float4 e = Er[c];
        float x0 = fmaxf(p.x + e.x, 0.f);
        float x1 = fmaxf(p.y + e.y, 0.f);
        float x2 = fmaxf(p.z + e.z, 0.f);
        float x3 = fmaxf(p.w + e.w, 0.f);
        atomicAdd(ag + 4 * c + 0, x0);
        atomicAdd(ag + 4 * c + 1, x1);
        atomicAdd(ag + 4 * c + 2, x2);
        atomicAdd(ag + 4 * c + 3, x3);
    }
}

// ------------------------- mol scatter: mol[batch[a]] += h_v[a] -------------------------
__global__ void mol_scatter(const float* __restrict__ hv, const int* __restrict__ batch,
                            float* __restrict__ mol) {
    int w = (blockIdx.x * blockDim.x + threadIdx.x) >> 5;
    int lane = threadIdx.x & 31;
    if (w >= N_ATOMS) return;
    int b = batch[w];
    const float4* hr = (const float4*)(hv + (size_t)w * NPAD);
    float* mr = mol + (size_t)b * NPAD;
    for (int c = lane; c < 75; c += 32) {
        float4 v = hr[c];
        atomicAdd(mr + 4 * c + 0, v.x);
        atomicAdd(mr + 4 * c + 1, v.y);
        atomicAdd(mr + 4 * c + 2, v.z);
        atomicAdd(mr + 4 * c + 3, v.w);
    }
}

// ------------------------- final: out = relu'd_ffn @ ffn2 + b2 -------------------------
__global__ void finalk(const float* __restrict__ F, const float* __restrict__ W2,
                       const float* __restrict__ b2, float* __restrict__ out) {
    int w = (blockIdx.x * blockDim.x + threadIdx.x) >> 5;
    int lane = threadIdx.x & 31;
    if (w >= N_MOLS) return;
    float acc = (lane < 12) ? b2[lane] : 0.f;
    const float* f = F + (size_t)w * NPAD;
    for (int j = 0; j < HIDDEN; j++) {
        float fv = __ldg(f + j);
        if (lane < 12) acc = fmaf(fv, W2[j * 12 + lane], acc);
    }
    if (lane < 12) out[w * 12 + lane] = acc;
}

// ------------------------- host launch -------------------------
static inline dim3 rep_grid(int n) { return dim3((n + 255) / 256); }

extern "C" void kernel_launch(void* const* d_in, const int* in_sizes, int n_in,
                              void* d_out, int out_size) {
    const float* x      = (const float*)d_in[0];
    const int*   ei     = (const int*)  d_in[1];   // [2, N_EDGES]
    const float* ea     = (const float*)d_in[2];
    const int*   batch  = (const int*)  d_in[3];
    const float* atom_W = (const float*)d_in[4];
    const float* atom_b = (const float*)d_in[5];
    // d_in[6], d_in[7]: bond_W / bond_b  -> dead code
    const float* Wi     = (const float*)d_in[8];
    // d_in[9]: Wh -> dead code
    const float* Wo     = (const float*)d_in[10];
    const float* Wo_b   = (const float*)d_in[11];
    const float* ffn1_W = (const float*)d_in[12];
    const float* ffn1_b = (const float*)d_in[13];
    const float* ffn2_W = (const float*)d_in[14];
    const float* ffn2_b = (const float*)d_in[15];
    float* out = (float*)d_out;

    float *p_xpad, *p_eapad, *p_hv, *p_hv2, *p_P, *p_agg, *p_E, *p_mol, *p_ffn;
    float *p_atomW, *p_WiTop, *p_WiBot, *p_Wo, *p_ffn1;
    float *p_atomB, *p_WoB, *p_ffn1B, *p_zeros;
    cudaGetSymbolAddress((void**)&p_xpad,  g_xpad);
    cudaGetSymbolAddress((void**)&p_eapad, g_eapad);
    cudaGetSymbolAddress((void**)&p_hv,    g_hv);
    cudaGetSymbolAddress((void**)&p_hv2,   g_hv2);
    cudaGetSymbolAddress((void**)&p_P,     g_P);
    cudaGetSymbolAddress((void**)&p_agg,   g_agg);
    cudaGetSymbolAddress((void**)&p_E,     g_E);
    cudaGetSymbolAddress((void**)&p_mol,   g_mol);
    cudaGetSymbolAddress((void**)&p_ffn,   g_ffn);
    cudaGetSymbolAddress((void**)&p_atomW, g_atomW);
    cudaGetSymbolAddress((void**)&p_WiTop, g_WiTop);
    cudaGetSymbolAddress((void**)&p_WiBot, g_WiBot);
    cudaGetSymbolAddress((void**)&p_Wo,    g_Wo);
    cudaGetSymbolAddress((void**)&p_ffn1,  g_ffn1);
    cudaGetSymbolAddress((void**)&p_atomB, g_atomB);
    cudaGetSymbolAddress((void**)&p_WoB,   g_WoB);
    cudaGetSymbolAddress((void**)&p_ffn1B, g_ffn1B);
    cudaGetSymbolAddress((void**)&p_zeros, g_zeros);

    // ---- repack inputs / weights into padded layouts ----
    repack<<<rep_grid(N_ATOMS * KX), 256>>>(p_xpad, x, N_ATOMS, KX, N_ATOMS, ATOM_FDIM, 0);
    repack<<<rep_grid(N_EDGES * KE), 256>>>(p_eapad, ea, N_EDGES, KE, N_EDGES, BOND_FDIM, 0);
    repack<<<rep_grid(KX * NPAD), 256>>>(p_atomW, atom_W, KX, NPAD, ATOM_FDIM, HIDDEN, 0);
    repack<<<rep_grid(KH * NPAD), 256>>>(p_WiTop, Wi, KH, NPAD, HIDDEN, HIDDEN, 0);
    repack<<<rep_grid(KE * NPAD), 256>>>(p_WiBot, Wi, KE, NPAD, BOND_FDIM, HIDDEN, HIDDEN);
    repack<<<rep_grid(KH * NPAD), 256>>>(p_Wo, Wo, KH, NPAD, HIDDEN, HIDDEN, 0);
    repack<<<rep_grid(KH * NPAD), 256>>>(p_Wo + KH * NPAD, Wo, KH, NPAD, HIDDEN, HIDDEN, HIDDEN);
    repack<<<rep_grid(KH * NPAD), 256>>>(p_ffn1, ffn1_W, KH, NPAD, HIDDEN, HIDDEN, 0);
    repack<<<rep_grid(NPAD), 256>>>(p_atomB, atom_b, 1, NPAD, 1, HIDDEN, 0);
    repack<<<rep_grid(NPAD), 256>>>(p_WoB, Wo_b, 1, NPAD, 1, HIDDEN, 0);
    repack<<<rep_grid(NPAD), 256>>>(p_ffn1B, ffn1_b, 1, NPAD, 1, HIDDEN, 0);

    dim3 gAtom((N_ATOMS + BM - 1) / BM, NPAD / BN);
    dim3 gEdge((N_EDGES + BM - 1) / BM, NPAD / BN);
    dim3 gMol ((N_MOLS  + BM - 1) / BM, NPAD / BN);

    // h_v = relu(x @ atom_W + atom_b)
    gemm_tf32<<<gAtom, 256>>>(p_xpad, KX, KX, nullptr, 0, 0, p_atomW, p_atomB, p_hv, N_ATOMS, 1);
    // E = edge_attr @ Wi_bot   (loop-invariant)
    gemm_tf32<<<gEdge, 256>>>(p_eapad, KE, KE, nullptr, 0, 0, p_WiBot, p_zeros, p_E, N_EDGES, 0);

    int edge_blocks = (N_EDGES * 32 + 255) / 256;
    int atom_warp_blocks = (N_ATOMS * 32 + 255) / 256;

    float* cur = p_hv;
    float* nxt = p_hv2;
    for (int d = 0; d < 3; d++) {
        // P = h_v @ Wi_top
        gemm_tf32<<<gAtom, 256>>>(cur, NPAD, KH, nullptr, 0, 0, p_WiTop, p_zeros, p_P, N_ATOMS, 0);
        // agg = 0; agg[dst] += relu(P[src] + E)
        zerok<<<(N_ATOMS * NPAD / 4 + 255) / 256, 256>>>((float4*)p_agg, N_ATOMS * NPAD / 4);
        edge_scatter<<<edge_blocks, 256>>>(p_P, p_E, ei, ei + N_EDGES, p_agg);
        // h_v = relu([h_v, agg] @ Wo + Wo_b)
        gemm_tf32<<<gAtom, 256>>>(cur, NPAD, KH, p_agg, NPAD, KH, p_Wo, p_WoB, nxt, N_ATOMS, 1);
        float* t = cur; cur = nxt; nxt = t;
    }

    // mol_repr = segment_sum(h_v, batch)
    zerok<<<(N_MOLS * NPAD / 4 + 255) / 256, 256>>>((float4*)p_mol, N_MOLS * NPAD / 4);
    mol_scatter<<<atom_warp_blocks, 256>>>(cur, batch, p_mol);
    // ffn = relu(mol @ ffn1 + b1)
    gemm_tf32<<<gMol, 256>>>(p_mol, NPAD, KH, nullptr, 0, 0, p_ffn1, p_ffn1B, p_ffn, N_MOLS, 1);
    // out = ffn @ ffn2 + b2
    finalk<<<(N_MOLS * 32 + 255) / 256, 256>>>(p_ffn, ffn2_W, ffn2_b, out);
}

// round 5
// speedup vs baseline: 1.6303x; 1.0861x over previous
#include <cuda_runtime.h>
#include <cstdint>

#define N_ATOMS 100000
#define N_ATOMS_PAD 102400   // multiple of 4096 for the scan
#define N_EDGES 400000
#define N_MOLS  4096
#define ATOM_FDIM 133
#define BOND_FDIM 14
#define HIDDEN 300
#define N_LABELS 12
#define NPAD 320        // padded hidden width
#define KX 144          // padded atom feature dim (multiple of 16)
#define KE 16           // padded bond feature dim
#define KH 304          // padded hidden as K-dim (multiple of 16)

#define BM 128
#define BN 64
#define BK 16

// ------------------------- scratch (static, no allocs) -------------------------
__device__ float g_xpad[(size_t)N_ATOMS * KX];
__device__ float g_hv  [(size_t)N_ATOMS * NPAD];
__device__ float g_hv2 [(size_t)N_ATOMS * NPAD];
__device__ float g_P   [(size_t)N_ATOMS * NPAD];
__device__ float g_agg [(size_t)N_ATOMS * NPAD];
__device__ float g_mol [(size_t)N_MOLS * NPAD];
__device__ float g_ffn [(size_t)N_MOLS * NPAD];

__device__ float g_atomW[KX * NPAD];
__device__ float g_WiTop[KH * NPAD];
__device__ float g_WiBot[KE * NPAD];
__device__ float g_Wo   [2 * KH * NPAD];
__device__ float g_ffn1 [KH * NPAD];
__device__ float g_atomB[NPAD];
__device__ float g_WoB  [NPAD];
__device__ float g_ffn1B[NPAD];
__device__ float g_zeros[NPAD];   // stays zero

// CSR scratch
__device__ int g_counts[N_ATOMS_PAD];
__device__ int g_rowptr[N_ATOMS_PAD + 1];
__device__ int g_cursor[N_ATOMS];
__device__ int g_esrc[N_EDGES];
__device__ int g_eid [N_EDGES];
__device__ int g_molptr[N_MOLS + 1];

// ------------------------- helpers -------------------------
__device__ __forceinline__ float tf32r(float x) {
    asm("cvt.rna.tf32.f32 %0, %0;" : "+f"(x));
    return x;
}

// ------------------------- repack: zero-padded copy -------------------------
__global__ void repack(float* __restrict__ dst, const float* __restrict__ src,
                       int dstR, int dstC, int srcR, int srcC, int srcRow0) {
    int idx = blockIdx.x * blockDim.x + threadIdx.x;
    if (idx >= dstR * dstC) return;
    int r = idx / dstC, c = idx - r * dstC;
    float v = 0.f;
    if (r < srcR && c < srcC) v = src[(size_t)(r + srcRow0) * srcC + c];
    dst[idx] = v;
}

__global__ void zeroI(int* __restrict__ p, int n) {
    int i = blockIdx.x * blockDim.x + threadIdx.x;
    if (i < n) p[i] = 0;
}

// ------------------------- CSR build -------------------------
__global__ void hist_dst(const int* __restrict__ dst, int* __restrict__ counts) {
    int e = blockIdx.x * blockDim.x + threadIdx.x;
    if (e < N_EDGES) atomicAdd(&counts[dst[e]], 1);
}

// single-block exclusive scan over N_ATOMS_PAD ints (1024 threads, 4096/chunk)
__global__ __launch_bounds__(1024)
void scan_counts(const int* __restrict__ counts, int* __restrict__ rowptr) {
    __shared__ int warp_sums[32];
    __shared__ int s_carry;
    const int tid = threadIdx.x;
    const int lane = tid & 31, wid = tid >> 5;
    if (tid == 0) s_carry = 0;
    __syncthreads();
    for (int base = 0; base < N_ATOMS_PAD; base += 4096) {
        int4 v = *(const int4*)(counts + base + tid * 4);
        int tsum = v.x + v.y + v.z + v.w;
        int val = tsum;
        #pragma unroll
        for (int off = 1; off < 32; off <<= 1) {
            int t = __shfl_up_sync(~0u, val, off);
            if (lane >= off) val += t;
        }
        if (lane == 31) warp_sums[wid] = val;
        __syncthreads();
        if (wid == 0) {
            int w = warp_sums[lane];
            #pragma unroll
            for (int off = 1; off < 32; off <<= 1) {
                int t = __shfl_up_sync(~0u, w, off);
                if (lane >= off) w += t;
            }
            warp_sums[lane] = w;
        }
        __syncthreads();
        int carry = s_carry;
        int excl = carry + (wid ? warp_sums[wid - 1] : 0) + (val - tsum);
        int idx = base + tid * 4;
        rowptr[idx + 0] = excl;
        rowptr[idx + 1] = excl + v.x;
        rowptr[idx + 2] = excl + v.x + v.y;
        rowptr[idx + 3] = excl + v.x + v.y + v.z;
        __syncthreads();
        if (tid == 0) s_carry = carry + warp_sums[31];
        __syncthreads();
    }
    if (threadIdx.x == 0) rowptr[N_ATOMS_PAD] = s_carry;
}

__global__ void copy_cursor(const int* __restrict__ rowptr, int* __restrict__ cursor) {
    int i = blockIdx.x * blockDim.x + threadIdx.x;
    if (i < N_ATOMS) cursor[i] = rowptr[i];
}

__global__ void fill_csr(const int* __restrict__ src, const int* __restrict__ dst,
                         int* __restrict__ cursor,
                         int* __restrict__ esrc, int* __restrict__ eid) {
    int e = blockIdx.x * blockDim.x + threadIdx.x;
    if (e >= N_EDGES) return;
    int d = dst[e];
    int pos = atomicAdd(&cursor[d], 1);
    esrc[pos] = src[e];
    eid[pos]  = e;
}

// batch is sorted -> molecule boundaries
__global__ void build_molptr(const int* __restrict__ batch, int* __restrict__ molptr) {
    int i = blockIdx.x * blockDim.x + threadIdx.x;
    if (i >= N_ATOMS) return;
    int b = batch[i];
    int bp = (i == 0) ? -1 : batch[i - 1];
    for (int m = bp + 1; m <= b; m++) molptr[m] = i;
    if (i == N_ATOMS - 1)
        for (int m = b + 1; m <= N_MOLS; m++) molptr[m] = N_ATOMS;
}

// ------------------------- tf32 tensor-core GEMM -------------------------
// C[M x 320] = relu?(A @ W + bias), A = virtual concat of A1 (K1 cols) and A2 (K2 cols).
__global__ __launch_bounds__(256)
void gemm_tf32(const float* __restrict__ A1, int lda1, int K1,
               const float* __restrict__ A2, int lda2, int K2,
               const float* __restrict__ W, const float* __restrict__ bias,
               float* __restrict__ C, int M, int doRelu) {
    __shared__ float As[BK][132];   // k-major, pad 132 -> conflict-free frag loads
    __shared__ float Bs[BK][68];    // k-major, pad 68

    const int tid  = threadIdx.x;
    const int lane = tid & 31;
    const int wid  = tid >> 5;
    const int warpM0 = (wid >> 1) << 5;   // 0,32,64,96
    const int warpN0 = (wid & 1) << 5;    // 0,32
    const int row0 = blockIdx.x * BM;
    const int n0   = blockIdx.y * BN;

    float acc[2][4][4];
    #pragma unroll
    for (int mt = 0; mt < 2; mt++)
        #pragma unroll
        for (int nt = 0; nt < 4; nt++)
            #pragma unroll
            for (int i = 0; i < 4; i++) acc[mt][nt][i] = 0.f;

    const int am  = tid >> 2;          // 0..63
    const int akq = (tid & 3) << 2;    // k base 0,4,8,12
    const int bkr = tid >> 4;          // 0..15
    const int bnc = (tid & 15) << 2;

    const int Ktot = K1 + K2;
    const int fr = lane >> 2;
    const int fc = lane & 3;

    float4 ar0, ar1, br;

    {
        const float* Asrc = (0 < K1) ? A1 : A2;
        int lda = (0 < K1) ? lda1 : lda2;
        int kb  = (0 < K1) ? 0 : -K1;
        int g0 = row0 + am;
        ar0 = make_float4(0.f, 0.f, 0.f, 0.f);
        ar1 = ar0;
        if (g0 < M)      ar0 = *(const float4*)(Asrc + (size_t)g0 * lda + kb + akq);
        if (g0 + 64 < M) ar1 = *(const float4*)(Asrc + (size_t)(g0 + 64) * lda + kb + akq);
        br = *(const float4*)(W + (size_t)bkr * NPAD + n0 + bnc);
    }

    for (int k0 = 0; k0 < Ktot; k0 += BK) {
        As[akq + 0][am] = tf32r(ar0.x);
        As[akq + 1][am] = tf32r(ar0.y);
        As[akq + 2][am] = tf32r(ar0.z);
        As[akq + 3][am] = tf32r(ar0.w);
        As[akq + 0][am + 64] = tf32r(ar1.x);
        As[akq + 1][am + 64] = tf32r(ar1.y);
        As[akq + 2][am + 64] = tf32r(ar1.z);
        As[akq + 3][am + 64] = tf32r(ar1.w);
        Bs[bkr][bnc + 0] = tf32r(br.x);
        Bs[bkr][bnc + 1] = tf32r(br.y);
        Bs[bkr][bnc + 2] = tf32r(br.z);
        Bs[bkr][bnc + 3] = tf32r(br.w);
        __syncthreads();

        int kn = k0 + BK;
        if (kn < Ktot) {
            const float* Asrc = (kn < K1) ? A1 : A2;
            int lda = (kn < K1) ? lda1 : lda2;
            int kb  = (kn < K1) ? kn : kn - K1;
            int g0 = row0 + am;
            ar0 = make_float4(0.f, 0.f, 0.f, 0.f);
            ar1 = ar0;
            if (g0 < M)      ar0 = *(const float4*)(Asrc + (size_t)g0 * lda + kb + akq);
            if (g0 + 64 < M) ar1 = *(const float4*)(Asrc + (size_t)(g0 + 64) * lda + kb + akq);
            br = *(const float4*)(W + (size_t)(kn + bkr) * NPAD + n0 + bnc);
        }

        #pragma unroll
        for (int ks = 0; ks < 2; ks++) {
            const int kk = ks * 8;
            uint32_t a[2][4], b[4][2];
            #pragma unroll
            for (int mt = 0; mt < 2; mt++) {
                int mr = warpM0 + mt * 16 + fr;
                a[mt][0] = __float_as_uint(As[kk + fc][mr]);
                a[mt][1] = __float_as_uint(As[kk + fc][mr + 8]);
                a[mt][2] = __float_as_uint(As[kk + fc + 4][mr]);
                a[mt][3] = __float_as_uint(As[kk + fc + 4][mr + 8]);
            }
            #pragma unroll
            for (int nt = 0; nt < 4; nt++) {
                int nc = warpN0 + nt * 8 + fr;
                b[nt][0] = __float_as_uint(Bs[kk + fc][nc]);
                b[nt][1] = __float_as_uint(Bs[kk + fc + 4][nc]);
            }
            #pragma unroll
            for (int mt = 0; mt < 2; mt++)
                #pragma unroll
                for (int nt = 0; nt < 4; nt++)
                    asm volatile(
                        "mma.sync.aligned.m16n8k8.row.col.f32.tf32.tf32.f32 "
                        "{%0,%1,%2,%3}, {%4,%5,%6,%7}, {%8,%9}, {%0,%1,%2,%3};"
                        : "+f"(acc[mt][nt][0]), "+f"(acc[mt][nt][1]),
                          "+f"(acc[mt][nt][2]), "+f"(acc[mt][nt][3])
                        : "r"(a[mt][0]), "r"(a[mt][1]), "r"(a[mt][2]), "r"(a[mt][3]),
                          "r"(b[nt][0]), "r"(b[nt][1]));
        }
        __syncthreads();
    }

    #pragma unroll
    for (int mt = 0; mt < 2; mt++) {
        int r = row0 + warpM0 + mt * 16 + fr;
        #pragma unroll
        for (int nt = 0; nt < 4; nt++) {
            int cbase = n0 + warpN0 + nt * 8 + (fc << 1);
            float2 bv = *(const float2*)&bias[cbase];
            if (r < M) {
                float2 v = make_float2(acc[mt][nt][0] + bv.x, acc[mt][nt][1] + bv.y);
                if (doRelu) { v.x = fmaxf(v.x, 0.f); v.y = fmaxf(v.y, 0.f); }
                *(float2*)(C + (size_t)r * NPAD + cbase) = v;
            }
            if (r + 8 < M) {
                float2 v = make_float2(acc[mt][nt][2] + bv.x, acc[mt][nt][3] + bv.y);
                if (doRelu) { v.x = fmaxf(v.x, 0.f); v.y = fmaxf(v.y, 0.f); }
                *(float2*)(C + (size_t)(r + 8) * NPAD + cbase) = v;
            }
        }
    }
}

// ------------------------- CSR gather: agg[v] = sum_in relu(P[src] + ea[e] @ WiBot) -----
// warp per atom; WiBot (14x320) in SMEM; E recomputed on the fly from edge_attr.
__global__ __launch_bounds__(256)
void gather_agg(const float* __restrict__ P, const float* __restrict__ ea,
                const float* __restrict__ WiBot,
                const int* __restrict__ rowptr, const int* __restrict__ esrc,
                const int* __restrict__ eid, float* __restrict__ agg) {
    __shared__ float Ws[14 * NPAD];
    for (int i = threadIdx.x; i < 14 * NPAD; i += 256) Ws[i] = WiBot[i];
    __syncthreads();

    int v = (blockIdx.x * 256 + threadIdx.x) >> 5;
    int lane = threadIdx.x & 31;
    if (v >= N_ATOMS) return;
    int beg = rowptr[v], end = rowptr[v + 1];

    float acc[10];
    #pragma unroll
    for (int j = 0; j < 10; j++) acc[j] = 0.f;

    for (int p = beg; p < end; p++) {
        int s = esrc[p];
        int e = eid[p];
        float eav = (lane < 14) ? __ldg(ea + (size_t)e * 14 + lane) : 0.f;
        float ef[14];
        #pragma unroll
        for (int f = 0; f < 14; f++) ef[f] = __shfl_sync(~0u, eav, f);
        const float* Pr = P + (size_t)s * NPAD;
        #pragma unroll
        for (int j = 0; j < 10; j++) {
            float m = Pr[lane + 32 * j];
            #pragma unroll
            for (int f = 0; f < 14; f++)
                m = fmaf(ef[f], Ws[f * NPAD + lane + 32 * j], m);
            acc[j] += fmaxf(m, 0.f);
        }
    }
    float* ag = agg + (size_t)v * NPAD;
    #pragma unroll
    for (int j = 0; j < 10; j++) ag[lane + 32 * j] = acc[j];
}

// ------------------------- molecule pooling (batch sorted -> contiguous ranges) -------
__global__ void mol_sum(const float* __restrict__ hv, const int* __restrict__ molptr,
                        float* __restrict__ mol) {
    int m = (blockIdx.x * blockDim.x + threadIdx.x) >> 5;
    int lane = threadIdx.x & 31;
    if (m >= N_MOLS) return;
    int beg = molptr[m], end = molptr[m + 1];
    float acc[10];
    #pragma unroll
    for (int j = 0; j < 10; j++) acc[j] = 0.f;
    for (int a = beg; a < end; a++) {
        const float* hr = hv + (size_t)a * NPAD;
        #pragma unroll
        for (int j = 0; j < 10; j++) acc[j] += hr[lane + 32 * j];
    }
    float* mr = mol + (size_t)m * NPAD;
    #pragma unroll
    for (int j = 0; j < 10; j++) mr[lane + 32 * j] = acc[j];
}

// ------------------------- final: out = relu'd_ffn @ ffn2 + b2 -------------------------
__global__ void finalk(const float* __restrict__ F, const float* __restrict__ W2,
                       const float* __restrict__ b2, float* __restrict__ out) {
    int w = (blockIdx.x * blockDim.x + threadIdx.x) >> 5;
    int lane = threadIdx.x & 31;
    if (w >= N_MOLS) return;
    float acc = (lane < 12) ? b2[lane] : 0.f;
    const float* f = F + (size_t)w * NPAD;
    for (int j = 0; j < HIDDEN; j++) {
        float fv = __ldg(f + j);
        if (lane < 12) acc = fmaf(fv, W2[j * 12 + lane], acc);
    }
    if (lane < 12) out[w * 12 + lane] = acc;
}

// ------------------------- host launch -------------------------
static inline dim3 rep_grid(int n) { return dim3((n + 255) / 256); }

extern "C" void kernel_launch(void* const* d_in, const int* in_sizes, int n_in,
                              void* d_out, int out_size) {
    const float* x      = (const float*)d_in[0];
    const int*   ei     = (const int*)  d_in[1];   // [2, N_EDGES]
    const float* ea     = (const float*)d_in[2];
    const int*   batch  = (const int*)  d_in[3];
    const float* atom_W = (const float*)d_in[4];
    const float* atom_b = (const float*)d_in[5];
    // d_in[6], d_in[7]: bond_W / bond_b  -> dead code
    const float* Wi     = (const float*)d_in[8];
    // d_in[9]: Wh -> dead code
    const float* Wo     = (const float*)d_in[10];
    const float* Wo_b   = (const float*)d_in[11];
    const float* ffn1_W = (const float*)d_in[12];
    const float* ffn1_b = (const float*)d_in[13];
    const float* ffn2_W = (const float*)d_in[14];
    const float* ffn2_b = (const float*)d_in[15];
    float* out = (float*)d_out;

    float *p_xpad, *p_hv, *p_hv2, *p_P, *p_agg, *p_mol, *p_ffn;
    float *p_atomW, *p_WiTop, *p_WiBot, *p_Wo, *p_ffn1;
    float *p_atomB, *p_WoB, *p_ffn1B, *p_zeros;
    int *p_counts, *p_rowptr, *p_cursor, *p_esrc, *p_eid, *p_molptr;
    cudaGetSymbolAddress((void**)&p_xpad,  g_xpad);
    cudaGetSymbolAddress((void**)&p_hv,    g_hv);
    cudaGetSymbolAddress((void**)&p_hv2,   g_hv2);
    cudaGetSymbolAddress((void**)&p_P,     g_P);
    cudaGetSymbolAddress((void**)&p_agg,   g_agg);
    cudaGetSymbolAddress((void**)&p_mol,   g_mol);
    cudaGetSymbolAddress((void**)&p_ffn,   g_ffn);
    cudaGetSymbolAddress((void**)&p_atomW, g_atomW);
    cudaGetSymbolAddress((void**)&p_WiTop, g_WiTop);
    cudaGetSymbolAddress((void**)&p_WiBot, g_WiBot);
    cudaGetSymbolAddress((void**)&p_Wo,    g_Wo);
    cudaGetSymbolAddress((void**)&p_ffn1,  g_ffn1);
    cudaGetSymbolAddress((void**)&p_atomB, g_atomB);
    cudaGetSymbolAddress((void**)&p_WoB,   g_WoB);
    cudaGetSymbolAddress((void**)&p_ffn1B, g_ffn1B);
    cudaGetSymbolAddress((void**)&p_zeros, g_zeros);
    cudaGetSymbolAddress((void**)&p_counts, g_counts);
    cudaGetSymbolAddress((void**)&p_rowptr, g_rowptr);
    cudaGetSymbolAddress((void**)&p_cursor, g_cursor);
    cudaGetSymbolAddress((void**)&p_esrc,   g_esrc);
    cudaGetSymbolAddress((void**)&p_eid,    g_eid);
    cudaGetSymbolAddress((void**)&p_molptr, g_molptr);

    const int* e_src = ei;
    const int* e_dst = ei + N_EDGES;

    // ---- repack inputs / weights into padded layouts ----
    repack<<<rep_grid(N_ATOMS * KX), 256>>>(p_xpad, x, N_ATOMS, KX, N_ATOMS, ATOM_FDIM, 0);
    repack<<<rep_grid(KX * NPAD), 256>>>(p_atomW, atom_W, KX, NPAD, ATOM_FDIM, HIDDEN, 0);
    repack<<<rep_grid(KH * NPAD), 256>>>(p_WiTop, Wi, KH, NPAD, HIDDEN, HIDDEN, 0);
    repack<<<rep_grid(KE * NPAD), 256>>>(p_WiBot, Wi, KE, NPAD, BOND_FDIM, HIDDEN, HIDDEN);
    repack<<<rep_grid(KH * NPAD), 256>>>(p_Wo, Wo, KH, NPAD, HIDDEN, HIDDEN, 0);
    repack<<<rep_grid(KH * NPAD), 256>>>(p_Wo + KH * NPAD, Wo, KH, NPAD, HIDDEN, HIDDEN, HIDDEN);
    repack<<<rep_grid(KH * NPAD), 256>>>(p_ffn1, ffn1_W, KH, NPAD, HIDDEN, HIDDEN, 0);
    repack<<<rep_grid(NPAD), 256>>>(p_atomB, atom_b, 1, NPAD, 1, HIDDEN, 0);
    repack<<<rep_grid(NPAD), 256>>>(p_WoB, Wo_b, 1, NPAD, 1, HIDDEN, 0);
    repack<<<rep_grid(NPAD), 256>>>(p_ffn1B, ffn1_b, 1, NPAD, 1, HIDDEN, 0);

    // ---- CSR build (by dst) + mol boundaries ----
    zeroI<<<rep_grid(N_ATOMS_PAD), 256>>>(p_counts, N_ATOMS_PAD);
    hist_dst<<<rep_grid(N_EDGES), 256>>>(e_dst, p_counts);
    scan_counts<<<1, 1024>>>(p_counts, p_rowptr);
    copy_cursor<<<rep_grid(N_ATOMS), 256>>>(p_rowptr, p_cursor);
    fill_csr<<<rep_grid(N_EDGES), 256>>>(e_src, e_dst, p_cursor, p_esrc, p_eid);
    build_molptr<<<rep_grid(N_ATOMS), 256>>>(batch, p_molptr);

    dim3 gAtom((N_ATOMS + BM - 1) / BM, NPAD / BN);
    dim3 gMol ((N_MOLS  + BM - 1) / BM, NPAD / BN);

    // h_v = relu(x @ atom_W + atom_b)
    gemm_tf32<<<gAtom, 256>>>(p_xpad, KX, KX, nullptr, 0, 0, p_atomW, p_atomB, p_hv, N_ATOMS, 1);

    int gather_blocks = (N_ATOMS * 32 + 255) / 256;

    float* cur = p_hv;
    float* nxt = p_hv2;
    for (int d = 0; d < 3; d++) {
        // P = h_v @ Wi_top
        gemm_tf32<<<gAtom, 256>>>(cur, NPAD, KH, nullptr, 0, 0, p_WiTop, p_zeros, p_P, N_ATOMS, 0);
        // agg[v] = sum over in-edges of relu(P[src] + edge_attr @ WiBot)   (no atomics)
        gather_agg<<<gather_blocks, 256>>>(p_P, ea, p_WiBot, p_rowptr, p_esrc, p_eid, p_agg);
        // h_v = relu([h_v, agg] @ Wo + Wo_b)
        gemm_tf32<<<gAtom, 256>>>(cur, NPAD, KH, p_agg, NPAD, KH, p_Wo, p_WoB, nxt, N_ATOMS, 1);
        float* t = cur; cur = nxt; nxt = t;
    }

    // mol_repr = segment_sum(h_v, batch) — contiguous ranges, no atomics
    mol_sum<<<(N_MOLS * 32 + 255) / 256, 256>>>(cur, p_molptr, p_mol);
    // ffn = relu(mol @ ffn1 + b1)
    gemm_tf32<<<gMol, 256>>>(p_mol, NPAD, KH, nullptr, 0, 0, p_ffn1, p_ffn1B, p_ffn, N_MOLS, 1);
    // out = ffn @ ffn2 + b2
    finalk<<<(N_MOLS * 32 + 255) / 256, 256>>>(p_ffn, ffn2_W, ffn2_b, out);
}

// round 6
// speedup vs baseline: 2.2976x; 1.4093x over previous
#include <cuda_runtime.h>
#include <cstdint>

#define N_ATOMS 100000
#define N_ATOMS_PAD 102400   // multiple of 4096 for the scan
#define N_EDGES 400000
#define N_MOLS  4096
#define ATOM_FDIM 133
#define BOND_FDIM 14
#define HIDDEN 300
#define N_LABELS 12
#define NPAD 320        // padded hidden width
#define KX 144          // padded atom feature dim (multiple of 16)
#define KE 16           // padded bond feature dim
#define KH 304          // padded hidden as K-dim (multiple of 16)

#define BM 128
#define BN 160
#define BK 16
#define AS_STRIDE 20    // floats; banks (20*fr+fc)%32 all-distinct
#define BS_STRIDE 168   // floats; banks (8*fc+fr)%32 all-distinct; 672B row, 16B-multiple

// ------------------------- scratch (static, no allocs) -------------------------
__device__ float g_xpad[(size_t)N_ATOMS * KX];
__device__ float g_hv  [(size_t)N_ATOMS * NPAD];
__device__ float g_hv2 [(size_t)N_ATOMS * NPAD];
__device__ float g_P   [(size_t)N_ATOMS * NPAD];
__device__ float g_agg [(size_t)N_ATOMS * NPAD];
__device__ float g_mol [(size_t)N_MOLS * NPAD];
__device__ float g_ffn [(size_t)N_MOLS * NPAD];

__device__ float g_atomW[KX * NPAD];
__device__ float g_WiTop[KH * NPAD];
__device__ float g_WiBot[KE * NPAD];
__device__ float g_Wo   [2 * KH * NPAD];
__device__ float g_ffn1 [KH * NPAD];
__device__ float g_atomB[NPAD];
__device__ float g_WoB  [NPAD];
__device__ float g_ffn1B[NPAD];
__device__ float g_zeros[NPAD];   // stays zero

// CSR scratch
__device__ int g_counts[N_ATOMS_PAD];
__device__ int g_rowptr[N_ATOMS_PAD + 1];
__device__ int g_cursor[N_ATOMS];
__device__ int g_esrc[N_EDGES];
__device__ int g_eid [N_EDGES];
__device__ int g_molptr[N_MOLS + 1];

// ------------------------- helpers -------------------------
__device__ __forceinline__ float tf32r(float x) {
    asm("cvt.rna.tf32.f32 %0, %0;" : "+f"(x));
    return x;
}
__device__ __forceinline__ uint32_t smem_u32(const void* p) {
    return (uint32_t)__cvta_generic_to_shared(p);
}

// ------------------------- repack: zero-padded copy (+optional tf32 round) ------------
__global__ void repack(float* __restrict__ dst, const float* __restrict__ src,
                       int dstR, int dstC, int srcR, int srcC, int srcRow0, int doRound) {
    int idx = blockIdx.x * blockDim.x + threadIdx.x;
    if (idx >= dstR * dstC) return;
    int r = idx / dstC, c = idx - r * dstC;
    float v = 0.f;
    if (r < srcR && c < srcC) v = src[(size_t)(r + srcRow0) * srcC + c];
    dst[idx] = doRound ? tf32r(v) : v;
}

__global__ void zeroI(int* __restrict__ p, int n) {
    int i = blockIdx.x * blockDim.x + threadIdx.x;
    if (i < n) p[i] = 0;
}

// ------------------------- CSR build -------------------------
__global__ void hist_dst(const int* __restrict__ dst, int* __restrict__ counts) {
    int e = blockIdx.x * blockDim.x + threadIdx.x;
    if (e < N_EDGES) atomicAdd(&counts[dst[e]], 1);
}

__global__ __launch_bounds__(1024)
void scan_counts(const int* __restrict__ counts, int* __restrict__ rowptr) {
    __shared__ int warp_sums[32];
    __shared__ int s_carry;
    const int tid = threadIdx.x;
    const int lane = tid & 31, wid = tid >> 5;
    if (tid == 0) s_carry = 0;
    __syncthreads();
    for (int base = 0; base < N_ATOMS_PAD; base += 4096) {
        int4 v = *(const int4*)(counts + base + tid * 4);
        int tsum = v.x + v.y + v.z + v.w;
        int val = tsum;
        #pragma unroll
        for (int off = 1; off < 32; off <<= 1) {
            int t = __shfl_up_sync(~0u, val, off);
            if (lane >= off) val += t;
        }
        if (lane == 31) warp_sums[wid] = val;
        __syncthreads();
        if (wid == 0) {
            int w = warp_sums[lane];
            #pragma unroll
            for (int off = 1; off < 32; off <<= 1) {
                int t = __shfl_up_sync(~0u, w, off);
                if (lane >= off) w += t;
            }
            warp_sums[lane] = w;
        }
        __syncthreads();
        int carry = s_carry;
        int excl = carry + (wid ? warp_sums[wid - 1] : 0) + (val - tsum);
        int idx = base + tid * 4;
        rowptr[idx + 0] = excl;
        rowptr[idx + 1] = excl + v.x;
        rowptr[idx + 2] = excl + v.x + v.y;
        rowptr[idx + 3] = excl + v.x + v.y + v.z;
        __syncthreads();
        if (tid == 0) s_carry = carry + warp_sums[31];
        __syncthreads();
    }
    if (threadIdx.x == 0) rowptr[N_ATOMS_PAD] = s_carry;
}

__global__ void copy_cursor(const int* __restrict__ rowptr, int* __restrict__ cursor) {
    int i = blockIdx.x * blockDim.x + threadIdx.x;
    if (i < N_ATOMS) cursor[i] = rowptr[i];
}

__global__ void fill_csr(const int* __restrict__ src, const int* __restrict__ dst,
                         int* __restrict__ cursor,
                         int* __restrict__ esrc, int* __restrict__ eid) {
    int e = blockIdx.x * blockDim.x + threadIdx.x;
    if (e >= N_EDGES) return;
    int d = dst[e];
    int pos = atomicAdd(&cursor[d], 1);
    esrc[pos] = src[e];
    eid[pos]  = e;
}

__global__ void build_molptr(const int* __restrict__ batch, int* __restrict__ molptr) {
    int i = blockIdx.x * blockDim.x + threadIdx.x;
    if (i >= N_ATOMS) return;
    int b = batch[i];
    int bp = (i == 0) ? -1 : batch[i - 1];
    for (int m = bp + 1; m <= b; m++) molptr[m] = i;
    if (i == N_ATOMS - 1)
        for (int m = b + 1; m <= N_MOLS; m++) molptr[m] = N_ATOMS;
}

// ------------------------- tf32 tensor-core GEMM -------------------------
// C[M x 320] = round_tf32(relu?(A @ W + bias)).
// A = virtual concat of A1 (K1 cols) and A2 (K2 cols); inputs assumed pre-rounded.
// Block tile 128x160, BK=16, cp.async double-buffered.
// 8 warps in 2(m) x 4(n); warp tile 64x40 (4 m16-tiles x 5 n8-tiles).
__global__ __launch_bounds__(256)
void gemm_tf32(const float* __restrict__ A1, int lda1, int K1,
               const float* __restrict__ A2, int lda2, int K2,
               const float* __restrict__ W, const float* __restrict__ bias,
               float* __restrict__ C, int M, int doRelu) {
    __shared__ float As[2][BM][AS_STRIDE];   // m-major
    __shared__ float Bs[2][BK][BS_STRIDE];   // k-major

    const int tid  = threadIdx.x;
    const int lane = tid & 31;
    const int wid  = tid >> 5;
    const int wm0  = (wid >> 2) * 64;   // 0,64
    const int wn0  = (wid & 3) * 40;    // 0,40,80,120
    const int row0 = blockIdx.x * BM;
    const int n0   = blockIdx.y * BN;
    const int fr = lane >> 2;
    const int fc = lane & 3;
    const int Ktot = K1 + K2;
    const int niter = Ktot / BK;

    float acc[4][5][4];
    #pragma unroll
    for (int mt = 0; mt < 4; mt++)
        #pragma unroll
        for (int nt = 0; nt < 5; nt++)
            #pragma unroll
            for (int i = 0; i < 4; i++) acc[mt][nt][i] = 0.f;

    // ---- async staging of tile k0 into buffer buf ----
    auto stage = [&](int k0, int buf) {
        const float* Asrc; int lda, kb;
        if (k0 < K1) { Asrc = A1; lda = lda1; kb = k0; }
        else         { Asrc = A2; lda = lda2; kb = k0 - K1; }
        // A tile: 128 rows x 16 k = 512 16B-chunks, 2 per thread
        #pragma unroll
        for (int j = 0; j < 2; j++) {
            int chunk = tid + j * 256;
            int m = chunk >> 2, kq = (chunk & 3) << 2;
            int g = row0 + m;
            const float* src = Asrc + (size_t)g * lda + kb + kq;
            uint32_t dst = smem_u32(&As[buf][m][kq]);
            int ss = (g < M) ? 16 : 0;
            asm volatile("cp.async.cg.shared.global [%0], [%1], 16, %2;"
                         :: "r"(dst), "l"(src), "r"(ss));
        }
        // B tile: 16 rows x 160 cols = 640 16B-chunks
        #pragma unroll
        for (int j = 0; j < 3; j++) {
            int chunk = tid + j * 256;
            if (chunk < 640) {
                int r = chunk / 40, c4 = (chunk - r * 40) << 2;
                const float* src = W + (size_t)(k0 + r) * NPAD + n0 + c4;
                uint32_t dst = smem_u32(&Bs[buf][r][c4]);
                asm volatile("cp.async.cg.shared.global [%0], [%1], 16;"
                             :: "r"(dst), "l"(src));
            }
        }
        asm volatile("cp.async.commit_group;");
    };

    stage(0, 0);

    for (int it = 0; it < niter; it++) {
        int buf = it & 1;
        bool more = (it + 1 < niter);
        if (more) stage((it + 1) * BK, buf ^ 1);
        if (more) asm volatile("cp.async.wait_group 1;");
        else      asm volatile("cp.async.wait_group 0;");
        __syncthreads();

        #pragma unroll
        for (int ks = 0; ks < 2; ks++) {
            const int kk = ks * 8;
            uint32_t a[4][4], b[5][2];
            #pragma unroll
            for (int mt = 0; mt < 4; mt++) {
                int mr = wm0 + mt * 16 + fr;
                a[mt][0] = __float_as_uint(As[buf][mr][kk + fc]);
                a[mt][1] = __float_as_uint(As[buf][mr + 8][kk + fc]);
                a[mt][2] = __float_as_uint(As[buf][mr][kk + fc + 4]);
                a[mt][3] = __float_as_uint(As[buf][mr + 8][kk + fc + 4]);
            }
            #pragma unroll
            for (int nt = 0; nt < 5; nt++) {
                int nc = wn0 + nt * 8 + fr;
                b[nt][0] = __float_as_uint(Bs[buf][kk + fc][nc]);
                b[nt][1] = __float_as_uint(Bs[buf][kk + fc + 4][nc]);
            }
            #pragma unroll
            for (int mt = 0; mt < 4; mt++)
                #pragma unroll
                for (int nt = 0; nt < 5; nt++)
                    asm volatile(
                        "mma.sync.aligned.m16n8k8.row.col.f32.tf32.tf32.f32 "
                        "{%0,%1,%2,%3}, {%4,%5,%6,%7}, {%8,%9}, {%0,%1,%2,%3};"
                        : "+f"(acc[mt][nt][0]), "+f"(acc[mt][nt][1]),
                          "+f"(acc[mt][nt][2]), "+f"(acc[mt][nt][3])
                        : "r"(a[mt][0]), "r"(a[mt][1]), "r"(a[mt][2]), "r"(a[mt][3]),
                          "r"(b[nt][0]), "r"(b[nt][1]));
        }
        __syncthreads();
    }

    // epilogue: bias + relu? + tf32 round
    #pragma unroll
    for (int mt = 0; mt < 4; mt++) {
        int r = row0 + wm0 + mt * 16 + fr;
        #pragma unroll
        for (int nt = 0; nt < 5; nt++) {
            int cbase = n0 + wn0 + nt * 8 + (fc << 1);
            float2 bv = *(const float2*)&bias[cbase];
            if (r < M) {
                float2 v = make_float2(acc[mt][nt][0] + bv.x, acc[mt][nt][1] + bv.y);
                if (doRelu) { v.x = fmaxf(v.x, 0.f); v.y = fmaxf(v.y, 0.f); }
                v.x = tf32r(v.x); v.y = tf32r(v.y);
                *(float2*)(C + (size_t)r * NPAD + cbase) = v;
            }
            if (r + 8 < M) {
                float2 v = make_float2(acc[mt][nt][2] + bv.x, acc[mt][nt][3] + bv.y);
                if (doRelu) { v.x = fmaxf(v.x, 0.f); v.y = fmaxf(v.y, 0.f); }
                v.x = tf32r(v.x); v.y = tf32r(v.y);
                *(float2*)(C + (size_t)(r + 8) * NPAD + cbase) = v;
            }
        }
    }
}

// ------------------------- CSR gather: agg[v] = sum_in relu(P[src] + ea[e] @ WiBot) -----
__global__ __launch_bounds__(256)
void gather_agg(const float* __restrict__ P, const float* __restrict__ ea,
                const float* __restrict__ WiBot,
                const int* __restrict__ rowptr, const int* __restrict__ esrc,
                const int* __restrict__ eid, float* __restrict__ agg) {
    __shared__ float Ws[14 * NPAD];
    for (int i = threadIdx.x; i < 14 * NPAD; i += 256) Ws[i] = WiBot[i];
    __syncthreads();

    int v = (blockIdx.x * 256 + threadIdx.x) >> 5;
    int lane = threadIdx.x & 31;
    if (v >= N_ATOMS) return;
    int beg = rowptr[v], end = rowptr[v + 1];

    float acc[10];
    #pragma unroll
    for (int j = 0; j < 10; j++) acc[j] = 0.f;

    for (int p = beg; p < end; p++) {
        int s = esrc[p];
        int e = eid[p];
        float eav = (lane < 14) ? __ldg(ea + (size_t)e * 14 + lane) : 0.f;
        float ef[14];
        #pragma unroll
        for (int f = 0; f < 14; f++) ef[f] = __shfl_sync(~0u, eav, f);
        const float* Pr = P + (size_t)s * NPAD;
        #pragma unroll
        for (int j = 0; j < 10; j++) {
            float m = Pr[lane + 32 * j];
            #pragma unroll
            for (int f = 0; f < 14; f++)
                m = fmaf(ef[f], Ws[f * NPAD + lane + 32 * j], m);
            acc[j] += fmaxf(m, 0.f);
        }
    }
    float* ag = agg + (size_t)v * NPAD;
    #pragma unroll
    for (int j = 0; j < 10; j++) ag[lane + 32 * j] = tf32r(acc[j]);
}

// ------------------------- molecule pooling (contiguous ranges) -------
__global__ void mol_sum(const float* __restrict__ hv, const int* __restrict__ molptr,
                        float* __restrict__ mol) {
    int m = (blockIdx.x * blockDim.x + threadIdx.x) >> 5;
    int lane = threadIdx.x & 31;
    if (m >= N_MOLS) return;
    int beg = molptr[m], end = molptr[m + 1];
    float acc[10];
    #pragma unroll
    for (int j = 0; j < 10; j++) acc[j] = 0.f;
    for (int a = beg; a < end; a++) {
        const float* hr = hv + (size_t)a * NPAD;
        #pragma unroll
        for (int j = 0; j < 10; j++) acc[j] += hr[lane + 32 * j];
    }
    float* mr = mol + (size_t)m * NPAD;
    #pragma unroll
    for (int j = 0; j < 10; j++) mr[lane + 32 * j] = tf32r(acc[j]);
}

// ------------------------- final: out = ffn @ ffn2 + b2 -------------------------
__global__ void finalk(const float* __restrict__ F, const float* __restrict__ W2,
                       const float* __restrict__ b2, float* __restrict__ out) {
    int w = (blockIdx.x * blockDim.x + threadIdx.x) >> 5;
    int lane = threadIdx.x & 31;
    if (w >= N_MOLS) return;
    float acc = (lane < 12) ? b2[lane] : 0.f;
    const float* f = F + (size_t)w * NPAD;
    for (int j = 0; j < HIDDEN; j++) {
        float fv = __ldg(f + j);
        if (lane < 12) acc = fmaf(fv, W2[j * 12 + lane], acc);
    }
    if (lane < 12) out[w * 12 + lane] = acc;
}

// ------------------------- host launch -------------------------
static inline dim3 rep_grid(int n) { return dim3((n + 255) / 256); }

extern "C" void kernel_launch(void* const* d_in, const int* in_sizes, int n_in,
                              void* d_out, int out_size) {
    const float* x      = (const float*)d_in[0];
    const int*   ei     = (const int*)  d_in[1];   // [2, N_EDGES]
    const float* ea     = (const float*)d_in[2];
    const int*   batch  = (const int*)  d_in[3];
    const float* atom_W = (const float*)d_in[4];
    const float* atom_b = (const float*)d_in[5];
    // d_in[6], d_in[7]: bond_W / bond_b  -> dead code
    const float* Wi     = (const float*)d_in[8];
    // d_in[9]: Wh -> dead code
    const float* Wo     = (const float*)d_in[10];
    const float* Wo_b   = (const float*)d_in[11];
    const float* ffn1_W = (const float*)d_in[12];
    const float* ffn1_b = (const float*)d_in[13];
    const float* ffn2_W = (const float*)d_in[14];
    const float* ffn2_b = (const float*)d_in[15];
    float* out = (float*)d_out;

    float *p_xpad, *p_hv, *p_hv2, *p_P, *p_agg, *p_mol, *p_ffn;
    float *p_atomW, *p_WiTop, *p_WiBot, *p_Wo, *p_ffn1;
    float *p_atomB, *p_WoB, *p_ffn1B, *p_zeros;
    int *p_counts, *p_rowptr, *p_cursor, *p_esrc, *p_eid, *p_molptr;
    cudaGetSymbolAddress((void**)&p_xpad,  g_xpad);
    cudaGetSymbolAddress((void**)&p_hv,    g_hv);
    cudaGetSymbolAddress((void**)&p_hv2,   g_hv2);
    cudaGetSymbolAddress((void**)&p_P,     g_P);
    cudaGetSymbolAddress((void**)&p_agg,   g_agg);
    cudaGetSymbolAddress((void**)&p_mol,   g_mol);
    cudaGetSymbolAddress((void**)&p_ffn,   g_ffn);
    cudaGetSymbolAddress((void**)&p_atomW, g_atomW);
    cudaGetSymbolAddress((void**)&p_WiTop, g_WiTop);
    cudaGetSymbolAddress((void**)&p_WiBot, g_WiBot);
    cudaGetSymbolAddress((void**)&p_Wo,    g_Wo);
    cudaGetSymbolAddress((void**)&p_ffn1,  g_ffn1);
    cudaGetSymbolAddress((void**)&p_atomB, g_atomB);
    cudaGetSymbolAddress((void**)&p_WoB,   g_WoB);
    cudaGetSymbolAddress((void**)&p_ffn1B, g_ffn1B);
    cudaGetSymbolAddress((void**)&p_zeros, g_zeros);
    cudaGetSymbolAddress((void**)&p_counts, g_counts);
    cudaGetSymbolAddress((void**)&p_rowptr, g_rowptr);
    cudaGetSymbolAddress((void**)&p_cursor, g_cursor);
    cudaGetSymbolAddress((void**)&p_esrc,   g_esrc);
    cudaGetSymbolAddress((void**)&p_eid,    g_eid);
    cudaGetSymbolAddress((void**)&p_molptr, g_molptr);

    const int* e_src = ei;
    const int* e_dst = ei + N_EDGES;

    // ---- repack inputs / weights (weights + x pre-rounded to tf32) ----
    repack<<<rep_grid(N_ATOMS * KX), 256>>>(p_xpad, x, N_ATOMS, KX, N_ATOMS, ATOM_FDIM, 0, 1);
    repack<<<rep_grid(KX * NPAD), 256>>>(p_atomW, atom_W, KX, NPAD, ATOM_FDIM, HIDDEN, 0, 1);
    repack<<<rep_grid(KH * NPAD), 256>>>(p_WiTop, Wi, KH, NPAD, HIDDEN, HIDDEN, 0, 1);
    repack<<<rep_grid(KE * NPAD), 256>>>(p_WiBot, Wi, KE, NPAD, BOND_FDIM, HIDDEN, HIDDEN, 1);
    repack<<<rep_grid(KH * NPAD), 256>>>(p_Wo, Wo, KH, NPAD, HIDDEN, HIDDEN, 0, 1);
    repack<<<rep_grid(KH * NPAD), 256>>>(p_Wo + KH * NPAD, Wo, KH, NPAD, HIDDEN, HIDDEN, HIDDEN, 1);
    repack<<<rep_grid(KH * NPAD), 256>>>(p_ffn1, ffn1_W, KH, NPAD, HIDDEN, HIDDEN, 0, 1);
    repack<<<rep_grid(NPAD), 256>>>(p_atomB, atom_b, 1, NPAD, 1, HIDDEN, 0, 0);
    repack<<<rep_grid(NPAD), 256>>>(p_WoB, Wo_b, 1, NPAD, 1, HIDDEN, 0, 0);
    repack<<<rep_grid(NPAD), 256>>>(p_ffn1B, ffn1_b, 1, NPAD, 1, HIDDEN, 0, 0);

    // ---- CSR build (by dst) + mol boundaries ----
    zeroI<<<rep_grid(N_ATOMS_PAD), 256>>>(p_counts, N_ATOMS_PAD);
    hist_dst<<<rep_grid(N_EDGES), 256>>>(e_dst, p_counts);
    scan_counts<<<1, 1024>>>(p_counts, p_rowptr);
    copy_cursor<<<rep_grid(N_ATOMS), 256>>>(p_rowptr, p_cursor);
    fill_csr<<<rep_grid(N_EDGES), 256>>>(e_src, e_dst, p_cursor, p_esrc, p_eid);
    build_molptr<<<rep_grid(N_ATOMS), 256>>>(batch, p_molptr);

    dim3 gAtom((N_ATOMS + BM - 1) / BM, NPAD / BN);
    dim3 gMol ((N_MOLS  + BM - 1) / BM, NPAD / BN);

    // h_v = relu(x @ atom_W + atom_b)
    gemm_tf32<<<gAtom, 256>>>(p_xpad, KX, KX, nullptr, 0, 0, p_atomW, p_atomB, p_hv, N_ATOMS, 1);

    int gather_blocks = (N_ATOMS * 32 + 255) / 256;

    float* cur = p_hv;
    float* nxt = p_hv2;
    for (int d = 0; d < 3; d++) {
        // P = h_v @ Wi_top
        gemm_tf32<<<gAtom, 256>>>(cur, NPAD, KH, nullptr, 0, 0, p_WiTop, p_zeros, p_P, N_ATOMS, 0);
        // agg[v] = sum over in-edges of relu(P[src] + edge_attr @ WiBot)
        gather_agg<<<gather_blocks, 256>>>(p_P, ea, p_WiBot, p_rowptr, p_esrc, p_eid, p_agg);
        // h_v = relu([h_v, agg] @ Wo + Wo_b)
        gemm_tf32<<<gAtom, 256>>>(cur, NPAD, KH, p_agg, NPAD, KH, p_Wo, p_WoB, nxt, N_ATOMS, 1);
        float* t = cur; cur = nxt; nxt = t;
    }

    // mol_repr = segment_sum(h_v, batch)
    mol_sum<<<(N_MOLS * 32 + 255) / 256, 256>>>(cur, p_molptr, p_mol);
    // ffn = relu(mol @ ffn1 + b1)
    gemm_tf32<<<gMol, 256>>>(p_mol, NPAD, KH, nullptr, 0, 0, p_ffn1, p_ffn1B, p_ffn, N_MOLS, 1);
    // out = ffn @ ffn2 + b2
    finalk<<<(N_MOLS * 32 + 255) / 256, 256>>>(p_ffn, ffn2_W, ffn2_b, out);
}